// round 4
// baseline (speedup 1.0000x reference)
#include <cuda_runtime.h>
#include <cuda_bf16.h>
#include <cstdint>

// TSM: x (B=4, T=16, H=64, W=64, C=256) fp32
// out[..., 0:64)    = x[t+1, ..., 0:64)   (0 at t=T-1)
// out[..., 64:128)  = x[t-1, ..., 64:128) (0 at t=0)
// out[..., 128:256) = x[t, ..., 128:256)
//
// R4: 256-bit global accesses (ld/st.global.v8.b32, sm_100+).
// float8 units: 32 per pixel (C=256 floats). c8 = i & 31.
//   dt = +1 (c8<8), -1 (c8<16), 0 otherwise.
// Slab stride (b,t) = 4096 pixels * 32 float8 = 1<<17 float8.

static constexpr int BTSTRIDE8 = 1 << 17;     // float8 per (b,t) slab
static constexpr long long N8 = 8388608LL;    // total float8
static constexpr int UNROLL = 4;
static constexpr int TPB = 256;
static constexpr int F8_PER_BLOCK = TPB * UNROLL; // 1024

__device__ __forceinline__ void ldg256_cs(const float* p, uint32_t* r)
{
    asm volatile("ld.global.cs.v8.b32 {%0,%1,%2,%3,%4,%5,%6,%7}, [%8];"
                 : "=r"(r[0]), "=r"(r[1]), "=r"(r[2]), "=r"(r[3]),
                   "=r"(r[4]), "=r"(r[5]), "=r"(r[6]), "=r"(r[7])
                 : "l"(p));
}

__device__ __forceinline__ void stg256_cs(float* p, const uint32_t* r)
{
    asm volatile("st.global.cs.v8.b32 [%0], {%1,%2,%3,%4,%5,%6,%7,%8};"
                 :: "l"(p),
                    "r"(r[0]), "r"(r[1]), "r"(r[2]), "r"(r[3]),
                    "r"(r[4]), "r"(r[5]), "r"(r[6]), "r"(r[7])
                 : "memory");
}

__global__ __launch_bounds__(TPB) void tsm_kernel(const float* __restrict__ in,
                                                  float* __restrict__ out)
{
    long long blockBase = (long long)(blockIdx.x) * F8_PER_BLOCK;
    int tid = threadIdx.x;

    uint32_t v[UNROLL][8];

    #pragma unroll
    for (int u = 0; u < UNROLL; ++u) {
        long long i = blockBase + u * TPB + tid;   // float8 index
        int c8 = (int)(i & 31);
        int t  = (int)((i >> 17) & 15);

        int dt = (c8 < 8) ? 1 : ((c8 < 16) ? -1 : 0);
        int ts = t + dt;
        bool valid = (unsigned)ts < 16u;

        #pragma unroll
        for (int k = 0; k < 8; ++k) v[u][k] = 0u;

        if (valid) {
            const float* p = in + ((i + (long long)dt * BTSTRIDE8) << 3);
            ldg256_cs(p, v[u]);
        }
    }

    #pragma unroll
    for (int u = 0; u < UNROLL; ++u) {
        long long i = blockBase + u * TPB + tid;
        stg256_cs(out + (i << 3), v[u]);
    }
}

extern "C" void kernel_launch(void* const* d_in, const int* in_sizes, int n_in,
                              void* d_out, int out_size)
{
    const float* in = (const float*)d_in[0];
    float* out = (float*)d_out;

    int blocks = (int)(N8 / F8_PER_BLOCK); // 8192
    tsm_kernel<<<blocks, TPB>>>(in, out);
}